// round 1
// baseline (speedup 1.0000x reference)
#include <cuda_runtime.h>
#include <cuda_bf16.h>

// Correlation cost volume:
// out[b, 9*i+j, h, w] = (1/C) * sum_c x1[b,c,h,w] * x2[b,c,h+i-4,w+j-4]
// B=4, C=256, H=96, W=192, 9x9 displacement grid, zero padding.

#define B_ 4
#define C_ 256
#define H_ 96
#define W_ 192
#define TH 4        // rows per block tile
#define TW 32       // cols per block tile
#define PW 4        // pixels per thread along w
#define CH 8        // channels per smem chunk
#define X2ROWS 12   // TH + 8
#define X2COLS 40   // TW + 8
#define X2STR 41    // padded stride (conflict-free)
#define X1STR 33    // padded stride (conflict-free)
#define NTHREADS 288  // (TW/PW) * TH * 9 = 8*4*9

__global__ __launch_bounds__(NTHREADS, 2)
void corr_kernel(const float* __restrict__ x1,
                 const float* __restrict__ x2,
                 float* __restrict__ out) {
    __shared__ float x2s[CH][X2ROWS][X2STR];
    __shared__ float x1s[CH][TH][X1STR];

    const int w0 = blockIdx.x * TW;   // 0..5 tiles
    const int h0 = blockIdx.y * TH;   // 0..23 tiles
    const int b  = blockIdx.z;

    const int tid  = threadIdx.x;
    const int di   = tid >> 5;        // warp id = row displacement 0..8
    const int lane = tid & 31;
    const int r    = lane & 3;        // row within tile 0..3
    const int wg   = lane >> 2;       // pixel group 0..7
    const int wbase = wg * PW;

    const float* x1g = x1 + (size_t)b * C_ * H_ * W_;
    const float* x2g = x2 + (size_t)b * C_ * H_ * W_;

    float acc[9][PW];
    #pragma unroll
    for (int dj = 0; dj < 9; ++dj)
        #pragma unroll
        for (int k = 0; k < PW; ++k) acc[dj][k] = 0.0f;

    for (int c0 = 0; c0 < C_; c0 += CH) {
        __syncthreads();
        // ---- load x1 tile: CH*TH*TW = 1024 elems ----
        #pragma unroll 1
        for (int idx = tid; idx < CH * TH * TW; idx += NTHREADS) {
            int c   = idx >> 7;        // /(TH*TW)=128
            int rem = idx & 127;
            int rr  = rem >> 5;        // /TW
            int cc  = rem & 31;
            x1s[c][rr][cc] = x1g[((size_t)(c0 + c) * H_ + (h0 + rr)) * W_ + w0 + cc];
        }
        // ---- load x2 extended tile (zero-padded): CH*12*40 = 3840 elems ----
        #pragma unroll 1
        for (int idx = tid; idx < CH * X2ROWS * X2COLS; idx += NTHREADS) {
            int c   = idx / (X2ROWS * X2COLS);
            int rem = idx % (X2ROWS * X2COLS);
            int rr  = rem / X2COLS;
            int cc  = rem % X2COLS;
            int gh  = h0 + rr - 4;
            int gw  = w0 + cc - 4;
            float v = 0.0f;
            if ((unsigned)gh < (unsigned)H_ && (unsigned)gw < (unsigned)W_)
                v = x2g[((size_t)(c0 + c) * H_ + gh) * W_ + gw];
            x2s[c][rr][cc] = v;
        }
        __syncthreads();

        // ---- compute: per channel, 4 x1 vals, 12-wide x2 window, 36 FMAs ----
        #pragma unroll
        for (int c = 0; c < CH; ++c) {
            float a[PW];
            #pragma unroll
            for (int k = 0; k < PW; ++k) a[k] = x1s[c][r][wbase + k];
            float xw[PW + 8];
            #pragma unroll
            for (int t = 0; t < PW + 8; ++t) xw[t] = x2s[c][r + di][wbase + t];
            #pragma unroll
            for (int dj = 0; dj < 9; ++dj)
                #pragma unroll
                for (int k = 0; k < PW; ++k)
                    acc[dj][k] = fmaf(a[k], xw[dj + k], acc[dj][k]);
        }
    }

    // ---- epilogue: scale by 1/C and store ----
    const float scale = 1.0f / (float)C_;
    #pragma unroll
    for (int dj = 0; dj < 9; ++dj) {
        const int d = di * 9 + dj;
        float* o = out + (((size_t)b * 81 + d) * H_ + (h0 + r)) * W_ + w0 + wbase;
        #pragma unroll
        for (int k = 0; k < PW; ++k) o[k] = acc[dj][k] * scale;
    }
}

extern "C" void kernel_launch(void* const* d_in, const int* in_sizes, int n_in,
                              void* d_out, int out_size) {
    const float* x1 = (const float*)d_in[0];
    const float* x2 = (const float*)d_in[1];
    float* out = (float*)d_out;

    dim3 grid(W_ / TW, H_ / TH, B_);   // (6, 24, 4)
    corr_kernel<<<grid, NTHREADS>>>(x1, x2, out);
}

// round 2
// speedup vs baseline: 4.5233x; 4.5233x over previous
#include <cuda_runtime.h>
#include <cuda_bf16.h>
#include <cstdint>

// Correlation cost volume:
// out[b, 9*i+j, h, w] = (1/C) * sum_c x1[b,c,h,w] * x2[b,c,h+i-4,w+j-4]
// B=4, C=256, H=96, W=192, 9x9 displacement grid, zero padding.

#define B_ 4
#define C_ 256
#define H_ 96
#define W_ 192
#define TH 4          // rows per block tile
#define TW 32         // cols per block tile
#define PW 4          // pixels per thread along w
#define CH 8          // channels per smem chunk
#define NCHUNK (C_ / CH)          // 32
#define X2ROWS 12                 // TH + 8
#define X2STR 56                  // 48 used cols [w0-8, w0+40) + 8 pad (conflict-free LDS.128)
#define X1STR 40                  // 32 used + 8 pad (conflict-free LDS.128)
#define X2BUF (CH * X2ROWS * X2STR)   // 5376 floats per buffer
#define X1BUF (CH * TH * X1STR)       // 1280 floats per buffer
#define SMEM_FLOATS (2 * X2BUF + 2 * X1BUF)   // 13312 floats = 53248 B
#define NTHREADS 288  // (TW/PW) * TH * 9 = 8*4*9
#define CHUNK_ELEMS (CH * H_ * W_)   // global float stride per channel-chunk

__device__ __forceinline__ void cp_async16(uint32_t dst, const float* src, int sz) {
    asm volatile("cp.async.cg.shared.global [%0], [%1], 16, %2;\n"
                 :: "r"(dst), "l"(src), "r"(sz));
}
__device__ __forceinline__ void cp_commit() {
    asm volatile("cp.async.commit_group;\n");
}
__device__ __forceinline__ void cp_wait1() {
    asm volatile("cp.async.wait_group 1;\n");
}

__global__ __launch_bounds__(NTHREADS, 2)
void corr_kernel(const float* __restrict__ x1,
                 const float* __restrict__ x2,
                 float* __restrict__ out) {
    extern __shared__ float smem[];
    float* sx2 = smem;                 // [2][CH][12][56]
    float* sx1 = smem + 2 * X2BUF;     // [2][CH][4][40]

    const int w0 = blockIdx.x * TW;
    const int h0 = blockIdx.y * TH;
    const int b  = blockIdx.z;

    const int tid  = threadIdx.x;
    const int di   = tid >> 5;        // warp id = row displacement 0..8
    const int lane = tid & 31;
    const int r    = lane & 3;        // row within tile 0..3
    const int wg   = lane >> 2;       // pixel group 0..7
    const int wbase = wg * PW;
    const int rdi  = r + di;          // x2 ext row 0..11

    const float* x1g = x1 + (size_t)b * C_ * H_ * W_;
    const float* x2g = x2 + (size_t)b * C_ * H_ * W_;

    const uint32_t sx2_u = (uint32_t)__cvta_generic_to_shared(sx2);
    const uint32_t sx1_u = (uint32_t)__cvta_generic_to_shared(sx1);

    // ---- precompute per-thread cp.async jobs (loop-invariant) ----
    // x2 ext tile: CH rows=12, cols: 12 float4 covering gw in [w0-8, w0+40)
    const float* x2src[4];
    uint32_t     x2dst[4];
    int          x2sz[4];
    #pragma unroll
    for (int s = 0; s < 4; ++s) {
        int qid    = tid + NTHREADS * s;        // 0..1151
        int row_id = qid / 12;                  // 0..95
        int q      = qid - row_id * 12;         // 0..11
        int c      = row_id / 12;               // 0..7
        int rr     = row_id - c * 12;           // 0..11
        int gh  = h0 + rr - 4;
        int gw0 = w0 - 8 + 4 * q;
        bool ok = ((unsigned)gh < (unsigned)H_) && (gw0 >= 0) && (gw0 <= W_ - 4);
        x2sz[s]  = ok ? 16 : 0;
        x2src[s] = ok ? (x2g + ((size_t)c * H_ + gh) * W_ + gw0) : x2g;
        x2dst[s] = sx2_u + (uint32_t)(((c * X2ROWS + rr) * X2STR + 4 * q) * 4);
    }
    // x1 tile: 256 float4 jobs, tid < 256
    const float* x1src = x1g;
    uint32_t     x1dst = 0;
    {
        int c  = tid >> 5;
        int rr = (tid >> 3) & 3;
        int q  = tid & 7;
        x1src = x1g + ((size_t)c * H_ + (h0 + rr)) * W_ + w0 + 4 * q;
        x1dst = sx1_u + (uint32_t)(((c * TH + rr) * X1STR + 4 * q) * 4);
    }
    const bool do_x1 = (tid < 256);

    float acc[9][PW];
    #pragma unroll
    for (int dj = 0; dj < 9; ++dj)
        #pragma unroll
        for (int k = 0; k < PW; ++k) acc[dj][k] = 0.0f;

    // ---- prologue: load chunk 0 into buffer 0 ----
    #pragma unroll
    for (int s = 0; s < 4; ++s) cp_async16(x2dst[s], x2src[s], x2sz[s]);
    if (do_x1) cp_async16(x1dst, x1src, 16);
    cp_commit();

    // ---- main pipelined loop ----
    for (int it = 0; it < NCHUNK; ++it) {
        // issue loads for chunk it+1 into the other buffer
        if (it + 1 < NCHUNK) {
            const size_t goff = (size_t)(it + 1) * CHUNK_ELEMS;
            const uint32_t bo2 = ((it + 1) & 1) ? (uint32_t)(X2BUF * 4) : 0u;
            const uint32_t bo1 = ((it + 1) & 1) ? (uint32_t)(X1BUF * 4) : 0u;
            #pragma unroll
            for (int s = 0; s < 4; ++s)
                cp_async16(x2dst[s] + bo2, x2src[s] + goff, x2sz[s]);
            if (do_x1) cp_async16(x1dst + bo1, x1src + goff, 16);
        }
        cp_commit();
        cp_wait1();          // chunk `it` resident
        __syncthreads();

        const float* cx1 = sx1 + (it & 1) * X1BUF + r * X1STR + wbase;
        const float* cx2 = sx2 + (it & 1) * X2BUF + rdi * X2STR + (wbase + 4);

        #pragma unroll
        for (int c = 0; c < CH; ++c) {
            const float4 av = *reinterpret_cast<const float4*>(cx1 + c * (TH * X1STR));
            const float4 v0 = *reinterpret_cast<const float4*>(cx2 + c * (X2ROWS * X2STR));
            const float4 v1 = *reinterpret_cast<const float4*>(cx2 + c * (X2ROWS * X2STR) + 4);
            const float4 v2 = *reinterpret_cast<const float4*>(cx2 + c * (X2ROWS * X2STR) + 8);
            float a[PW] = {av.x, av.y, av.z, av.w};
            float xw[12] = {v0.x, v0.y, v0.z, v0.w,
                            v1.x, v1.y, v1.z, v1.w,
                            v2.x, v2.y, v2.z, v2.w};
            #pragma unroll
            for (int dj = 0; dj < 9; ++dj)
                #pragma unroll
                for (int k = 0; k < PW; ++k)
                    acc[dj][k] = fmaf(a[k], xw[dj + k], acc[dj][k]);
        }
        __syncthreads();   // buffer (it&1) free for reuse at iter it+1
    }

    // ---- epilogue: scale by 1/C and store (float4) ----
    const float scale = 1.0f / (float)C_;
    #pragma unroll
    for (int dj = 0; dj < 9; ++dj) {
        const int d = di * 9 + dj;
        float4 v;
        v.x = acc[dj][0] * scale;
        v.y = acc[dj][1] * scale;
        v.z = acc[dj][2] * scale;
        v.w = acc[dj][3] * scale;
        float* o = out + (((size_t)b * 81 + d) * H_ + (h0 + r)) * W_ + w0 + wbase;
        *reinterpret_cast<float4*>(o) = v;
    }
}

extern "C" void kernel_launch(void* const* d_in, const int* in_sizes, int n_in,
                              void* d_out, int out_size) {
    const float* x1 = (const float*)d_in[0];
    const float* x2 = (const float*)d_in[1];
    float* out = (float*)d_out;

    static bool attr_set = false;
    if (!attr_set) {
        cudaFuncSetAttribute(corr_kernel,
                             cudaFuncAttributeMaxDynamicSharedMemorySize,
                             SMEM_FLOATS * (int)sizeof(float));
        attr_set = true;
    }

    dim3 grid(W_ / TW, H_ / TH, B_);   // (6, 24, 4)
    corr_kernel<<<grid, NTHREADS, SMEM_FLOATS * sizeof(float)>>>(x1, x2, out);
}